// round 1
// baseline (speedup 1.0000x reference)
#include <cuda_runtime.h>
#include <math.h>

// Problem constants
#define BB 4
#define CC 32
#define SS 64
#define MM 8
#define NT 262144   // 64^3
#define NCH 128     // B*C

// Scratch (device globals; no allocation allowed)
__device__ float g_ct[64];
__device__ float g_st[64];
__device__ float g_inv1[NCH];
__device__ float g_sc2[NCH];
__device__ float g_Ac[NCH*8*64*64];   // 16 MB
__device__ float g_As[NCH*8*64*64];   // 16 MB
__device__ float g_P [NCH*8*8*64];    // 2 MB
__device__ float g_Q [NCH*8*8*64];
__device__ float g_x1[NCH*512];
__device__ float g_y [NCH*512];
__device__ float g_wp[CC*CC*512];
__device__ float g_wm[CC*CC*512];
__device__ float g_tc[NCH*8*8*64];
__device__ float g_ts[NCH*8*8*64];
__device__ float g_P2[NCH*8*64*64];   // 16 MB
__device__ float g_Q2[NCH*8*64*64];   // 16 MB

// ---------------- tables ----------------
__global__ void k_init_tables() {
    int t = threadIdx.x;
    if (t < 64) {
        double a = (double)t * (M_PI / 32.0);   // 2*pi*t/64
        g_ct[t] = (float)cos(a);
        g_st[t] = (float)sin(a);
    }
}

// ---------------- weight prep: wp=(w+wn)/2, wm=(w-wn)/2 ----------------
__global__ void k_prep_w(const float* __restrict__ w) {
    int idx = blockIdx.x * blockDim.x + threadIdx.x;
    if (idx >= CC*CC*512) return;
    int k  = idx & 511;
    int io = idx >> 9;
    int k1 = k >> 6, k2 = (k >> 3) & 7, k3 = k & 7;
    int nk = (((8-k1)&7) << 6) | (((8-k2)&7) << 3) | ((8-k3)&7);
    float a = w[(io<<9) + k];
    float b = w[(io<<9) + nk];
    g_wp[idx] = 0.5f * (a + b);
    g_wm[idx] = 0.5f * (a - b);
}

// ---------------- norm1 via Parseval-like identity ----------------
// norm^2 = NT * ( sum x^2 + 0.5*(C0 - C2) )
// C0 = sum x[n]*x[(-n)%64 per dim]; C2 = sum x[n]*x[(-n1)%,(-n2)%,(-n3-2)%64]
__global__ void k_norm1(const float* __restrict__ x) {
    int bc = blockIdx.x;
    const float* xp = x + ((size_t)bc << 18);
    float s0 = 0.f, c0 = 0.f, c2 = 0.f;
    for (int idx = threadIdx.x; idx < NT; idx += blockDim.x) {
        int n1 = idx >> 12, n2 = (idx >> 6) & 63, n3 = idx & 63;
        int r1 = (64 - n1) & 63, r2 = (64 - n2) & 63;
        int r3 = (64 - n3) & 63, r3b = (126 - n3) & 63;  // (-n3-2) mod 64
        float v = xp[idx];
        s0 += v * v;
        c0 += v * xp[(r1 << 12) + (r2 << 6) + r3];
        c2 += v * xp[(r1 << 12) + (r2 << 6) + r3b];
    }
    __shared__ float sa[256], sb[256], sc[256];
    int t = threadIdx.x;
    sa[t] = s0; sb[t] = c0; sc[t] = c2;
    __syncthreads();
    for (int s = 128; s > 0; s >>= 1) {
        if (t < s) { sa[t] += sa[t+s]; sb[t] += sb[t+s]; sc[t] += sc[t+s]; }
        __syncthreads();
    }
    if (t == 0) {
        float v = (float)NT * (sa[0] + 0.5f * (sb[0] - sc[0]));
        g_inv1[bc] = (v > 0.f) ? rsqrtf(v) : 0.f;
    }
}

// ---------------- F1: contract n1 -> k1 (8 modes), cos & sin ----------------
__global__ void k_f1(const float* __restrict__ x) {
    __shared__ float s_ct[64], s_st[64];
    if (threadIdx.x < 64) { s_ct[threadIdx.x] = g_ct[threadIdx.x]; s_st[threadIdx.x] = g_st[threadIdx.x]; }
    __syncthreads();
    int bc = blockIdx.x;
    int n2 = blockIdx.y * 4 + (threadIdx.x >> 6);
    int n3 = threadIdx.x & 63;
    const float* xp = x + ((size_t)bc << 18) + (n2 << 6) + n3;
    float ac[8] = {0,0,0,0,0,0,0,0};
    float as_[8] = {0,0,0,0,0,0,0,0};
    for (int n1 = 0; n1 < 64; n1++) {
        float v = xp[n1 << 12];
        #pragma unroll
        for (int k1 = 0; k1 < 8; k1++) {
            int t = (k1 * n1) & 63;
            ac[k1]  = fmaf(v, s_ct[t], ac[k1]);
            as_[k1] = fmaf(v, s_st[t], as_[k1]);
        }
    }
    #pragma unroll
    for (int k1 = 0; k1 < 8; k1++) {
        int o = (((bc * 8 + k1) * 64 + n2) << 6) + n3;
        g_Ac[o] = ac[k1];
        g_As[o] = as_[k1];
    }
}

// ---------------- F2: contract n2 -> k2: P=sum x cos(a+b), Q=sum x sin(a+b) ----------------
__global__ void k_f2() {
    __shared__ float s_ct[64], s_st[64];
    if (threadIdx.x < 64) { s_ct[threadIdx.x] = g_ct[threadIdx.x]; s_st[threadIdx.x] = g_st[threadIdx.x]; }
    __syncthreads();
    int bc = blockIdx.x;
    int k1 = threadIdx.x >> 6;
    int n3 = threadIdx.x & 63;
    int base = ((bc * 8 + k1) << 12) + n3;   // + n2*64
    float p[8] = {0,0,0,0,0,0,0,0};
    float q[8] = {0,0,0,0,0,0,0,0};
    for (int n2 = 0; n2 < 64; n2++) {
        float acv = g_Ac[base + (n2 << 6)];
        float asv = g_As[base + (n2 << 6)];
        #pragma unroll
        for (int k2 = 0; k2 < 8; k2++) {
            int t = (k2 * n2) & 63;
            float c = s_ct[t], s = s_st[t];
            p[k2] = fmaf(acv, c, fmaf(-asv, s, p[k2]));
            q[k2] = fmaf(acv, s, fmaf( asv, c, q[k2]));
        }
    }
    #pragma unroll
    for (int k2 = 0; k2 < 8; k2++) {
        int o = (((bc * 8 + k1) * 8 + k2) << 6) + n3;
        g_P[o] = p[k2];
        g_Q[o] = q[k2];
    }
}

// ---------------- F3: contract n3 -> k3 with U,V; apply 1/norm1 ----------------
__global__ void k_f3() {
    __shared__ float s_ct[65], s_st[65];
    if (threadIdx.x < 64) { s_ct[threadIdx.x] = g_ct[threadIdx.x]; s_st[threadIdx.x] = g_st[threadIdx.x]; }
    __syncthreads();
    int bc = blockIdx.x;
    int k1 = threadIdx.x >> 6, k2 = (threadIdx.x >> 3) & 7, k3 = threadIdx.x & 7;
    int base = ((bc * 8 + k1) * 8 + k2) << 6;
    float h = 0.f;
    for (int n3 = 0; n3 < 64; n3++) {
        float pv = g_P[base + n3];
        float qv = g_Q[base + n3];
        int t0 = (k3 * n3) & 63;
        int t1 = (k3 * (n3 + 1)) & 63;
        // U = ct[t0]-st[t1], V = ct[t1]-st[t0]
        h += pv * (s_ct[t0] - s_st[t1]) + qv * (s_ct[t1] - s_st[t0]);
    }
    g_x1[bc * 512 + (k1 << 6) + (k2 << 3) + k3] = h * g_inv1[bc];
}

// ---------------- conv: channel mixing with symmetrized weights ----------------
__global__ void k_conv() {
    int bo = blockIdx.x;            // b*32 + o
    int b = bo >> 5, o = bo & 31;
    int k = threadIdx.x;
    int k1 = k >> 6, k2 = (k >> 3) & 7, k3 = k & 7;
    int nk = (((8-k1)&7) << 6) | (((8-k2)&7) << 3) | ((8-k3)&7);
    float acc = 0.f;
    for (int i = 0; i < 32; i++) {
        const float* x1p = g_x1 + ((b * 32 + i) << 9);
        int wb = (i * 32 + o) << 9;
        acc = fmaf(x1p[k],  g_wp[wb + k], acc);
        acc = fmaf(x1p[nk], g_wm[wb + k], acc);
    }
    g_y[(bo << 9) + k] = acc;
}

// ---------------- norm2: scale = 1/(sqrt(NT*(sum y^2 + 0.5*y000^2)) * NT) ----------------
__global__ void k_norm2() {
    int bo = blockIdx.x;
    float v = g_y[(bo << 9) + threadIdx.x];
    __shared__ float sa[512];
    sa[threadIdx.x] = v * v;
    __syncthreads();
    for (int s = 256; s > 0; s >>= 1) {
        if (threadIdx.x < s) sa[threadIdx.x] += sa[threadIdx.x + s];
        __syncthreads();
    }
    if (threadIdx.x == 0) {
        float y0 = g_y[bo << 9];
        float t = sa[0] + 0.5f * y0 * y0;
        g_sc2[bo] = (t > 0.f) ? rsqrtf((float)NT * t) / (float)NT : 0.f;
    }
}

// ---------------- I1: expand k3 -> j3 with U',V' (scale folded in) ----------------
__global__ void k_i1() {
    __shared__ float s_ct[65], s_st[65];
    if (threadIdx.x < 64) { s_ct[threadIdx.x] = g_ct[threadIdx.x]; s_st[threadIdx.x] = g_st[threadIdx.x]; }
    __syncthreads();
    int bo = blockIdx.x;
    int k1 = blockIdx.y;
    int k2 = threadIdx.x >> 6;
    int j3 = threadIdx.x & 63;
    float sc = g_sc2[bo];
    int ybase = (bo << 9) + (k1 << 6) + (k2 << 3);
    float tcv = 0.f, tsv = 0.f;
    #pragma unroll
    for (int k3 = 0; k3 < 8; k3++) {
        float yv = g_y[ybase + k3] * sc;
        int t0 = (j3 * k3) & 63;
        int t1 = (j3 * (k3 + 1)) & 63;
        tcv += yv * (s_ct[t0] - s_st[t1]);
        tsv += yv * (s_ct[t1] - s_st[t0]);
    }
    int o = (((bo * 8 + k1) * 8 + k2) << 6) + j3;
    g_tc[o] = tcv;
    g_ts[o] = tsv;
}

// ---------------- I2: expand k2 -> j2 ----------------
__global__ void k_i2() {
    __shared__ float s_ct[65], s_st[65];
    if (threadIdx.x < 64) { s_ct[threadIdx.x] = g_ct[threadIdx.x]; s_st[threadIdx.x] = g_st[threadIdx.x]; }
    __syncthreads();
    int bo = blockIdx.x;
    int k1 = blockIdx.y;
    int j2 = blockIdx.z * 8 + (threadIdx.x >> 6);
    int j3 = threadIdx.x & 63;
    int tbase = (((bo * 8 + k1) * 8) << 6) + j3;   // + k2*64
    float p = 0.f, q = 0.f;
    #pragma unroll
    for (int k2 = 0; k2 < 8; k2++) {
        float a = g_tc[tbase + (k2 << 6)];
        float s_ = g_ts[tbase + (k2 << 6)];
        int t = (j2 * k2) & 63;
        float c = s_ct[t], sn = s_st[t];
        p += a * c + s_ * sn;
        q += s_ * c - a * sn;
    }
    int o = (((bo * 8 + k1) * 64 + j2) << 6) + j3;
    g_P2[o] = p;
    g_Q2[o] = q;
}

// ---------------- I3: expand k1 -> j1, write final output ----------------
__global__ void k_i3(float* __restrict__ out) {
    __shared__ float s_ct[64], s_st[64];
    if (threadIdx.x < 64) { s_ct[threadIdx.x] = g_ct[threadIdx.x]; s_st[threadIdx.x] = g_st[threadIdx.x]; }
    __syncthreads();
    int bo = blockIdx.x;
    int j2 = blockIdx.y * 4 + (threadIdx.x >> 6);
    int j3 = threadIdx.x & 63;
    float p[8], q[8];
    #pragma unroll
    for (int k1 = 0; k1 < 8; k1++) {
        int o = (((bo * 8 + k1) * 64 + j2) << 6) + j3;
        p[k1] = g_P2[o];
        q[k1] = g_Q2[o];
    }
    float* op = out + ((size_t)bo << 18) + (j2 << 6) + j3;
    for (int j1 = 0; j1 < 64; j1++) {
        float acc = 0.f;
        #pragma unroll
        for (int k1 = 0; k1 < 8; k1++) {
            int t = (j1 * k1) & 63;
            acc = fmaf(p[k1], s_ct[t], acc);
            acc = fmaf(q[k1], s_st[t], acc);
        }
        op[j1 << 12] = acc;
    }
}

extern "C" void kernel_launch(void* const* d_in, const int* in_sizes, int n_in,
                              void* d_out, int out_size) {
    const float* x = (const float*)d_in[0];       // (4,32,64,64,64)
    const float* w = (const float*)d_in[1];       // (32,32,8,8,8)
    float* out = (float*)d_out;                   // (4,32,64,64,64)

    k_init_tables<<<1, 64>>>();
    k_prep_w<<<(CC*CC*512 + 255) / 256, 256>>>(w);
    k_norm1<<<NCH, 256>>>(x);
    k_f1<<<dim3(NCH, 16), 256>>>(x);
    k_f2<<<NCH, 512>>>();
    k_f3<<<NCH, 512>>>();
    k_conv<<<NCH, 512>>>();
    k_norm2<<<NCH, 512>>>();
    k_i1<<<dim3(NCH, 8), 512>>>();
    k_i2<<<dim3(NCH, 8, 8), 512>>>();
    k_i3<<<dim3(NCH, 16), 256>>>(out);
}

// round 2
// speedup vs baseline: 2.4595x; 2.4595x over previous
#include <cuda_runtime.h>
#include <math.h>

#define BB 4
#define CC 32
#define SS 64
#define MM 8
#define NT 262144   // 64^3
#define NCH 128     // B*C

// Scratch (device globals)
__device__ float g_ct[64];
__device__ float g_st[64];
__device__ float g_part[NCH * 4 * 3];     // per (bc,tile): s0,c0,c2
__device__ float g_Ac[NCH*8*64*64];       // 16 MB
__device__ float g_As[NCH*8*64*64];       // 16 MB
__device__ float g_P [NCH*8*8*64];        // 2 MB
__device__ float g_Q [NCH*8*8*64];
__device__ float g_x1[NCH*512];
__device__ float g_y [NCH*512];
__device__ float g_sc2[NCH];
__device__ float g_wp[CC*CC*512];
__device__ float g_wm[CC*CC*512];

// ---------------- tables ----------------
__global__ void k_init_tables() {
    int t = threadIdx.x;
    if (t < 64) {
        double a = (double)t * (M_PI / 32.0);
        g_ct[t] = (float)cos(a);
        g_st[t] = (float)sin(a);
    }
}

// ---------------- weight prep ----------------
__global__ void k_prep_w(const float* __restrict__ w) {
    int idx = blockIdx.x * blockDim.x + threadIdx.x;
    if (idx >= CC*CC*512) return;
    int k  = idx & 511;
    int io = idx >> 9;
    int k1 = k >> 6, k2 = (k >> 3) & 7, k3 = k & 7;
    int nk = (((8-k1)&7) << 6) | (((8-k2)&7) << 3) | ((8-k3)&7);
    float a = w[(io<<9) + k];
    float b = w[(io<<9) + nk];
    g_wp[idx] = 0.5f * (a + b);
    g_wm[idx] = 0.5f * (a - b);
}

// ---------------- F1 + norm1 fused ----------------
// Each thread handles 4 columns (n2 varies), all n1.
// Also accumulates s0 = sum x^2, c0 = sum x[n]x[-n], c2 = sum x[n]x[-n1,-n2,-n3-2]
__global__ void __launch_bounds__(256, 2) k_f1n(const float* __restrict__ x) {
    __shared__ float s_ct[64], s_st[64];
    __shared__ float s_red[3][8];
    int t = threadIdx.x;
    if (t < 64) { s_ct[t] = g_ct[t]; s_st[t] = g_st[t]; }
    __syncthreads();

    int tile = blockIdx.x;     // 0..3
    int bc   = blockIdx.y;     // 0..127
    int n3   = t & 63;
    int n2g  = t >> 6;         // 0..3
    int n2b  = tile * 16 + n2g * 4;
    int r3   = (64 - n3) & 63;
    int r3b  = (62 - n3) & 63;

    const float* xb = x + ((size_t)bc << 18);

    int offp[4], offr0[4], offr2[4];
    #pragma unroll
    for (int v = 0; v < 4; v++) {
        int n2 = n2b + v;
        int r2 = (64 - n2) & 63;
        offp[v]  = (n2 << 6) + n3;
        offr0[v] = (r2 << 6) + r3;
        offr2[v] = (r2 << 6) + r3b;
    }

    float ac[4][8], as_[4][7];
    #pragma unroll
    for (int v = 0; v < 4; v++) {
        #pragma unroll
        for (int k = 0; k < 8; k++) ac[v][k] = 0.f;
        #pragma unroll
        for (int k = 0; k < 7; k++) as_[v][k] = 0.f;
    }
    float s0 = 0.f, c0 = 0.f, c2 = 0.f;

    for (int n1 = 0; n1 < 64; n1++) {
        int rn1 = (64 - n1) & 63;
        float tc[7], ts[7];
        #pragma unroll
        for (int k = 1; k < 8; k++) {
            int tt = (k * n1) & 63;
            tc[k-1] = s_ct[tt];
            ts[k-1] = s_st[tt];
        }
        int po = n1 << 12, ro = rn1 << 12;
        #pragma unroll
        for (int v = 0; v < 4; v++) {
            float val = xb[po + offp[v]];
            float vr0 = xb[ro + offr0[v]];
            float vr2 = xb[ro + offr2[v]];
            s0 = fmaf(val, val, s0);
            c0 = fmaf(val, vr0, c0);
            c2 = fmaf(val, vr2, c2);
            ac[v][0] += val;
            #pragma unroll
            for (int k = 1; k < 8; k++) {
                ac[v][k]   = fmaf(val, tc[k-1], ac[v][k]);
                as_[v][k-1]= fmaf(val, ts[k-1], as_[v][k-1]);
            }
        }
    }

    // store Ac/As
    #pragma unroll
    for (int v = 0; v < 4; v++) {
        int n2 = n2b + v;
        #pragma unroll
        for (int k = 0; k < 8; k++) {
            int o = (((bc * 8 + k) * 64 + n2) << 6) + n3;
            g_Ac[o] = ac[v][k];
            g_As[o] = (k == 0) ? 0.f : as_[v][k-1];
        }
    }

    // block reduce s0,c0,c2 (deterministic per (bc,tile))
    unsigned m = 0xffffffffu;
    #pragma unroll
    for (int s = 16; s > 0; s >>= 1) {
        s0 += __shfl_down_sync(m, s0, s);
        c0 += __shfl_down_sync(m, c0, s);
        c2 += __shfl_down_sync(m, c2, s);
    }
    int lane = t & 31, wid = t >> 5;
    if (lane == 0) { s_red[0][wid] = s0; s_red[1][wid] = c0; s_red[2][wid] = c2; }
    __syncthreads();
    if (t == 0) {
        float a0 = 0, a1 = 0, a2 = 0;
        #pragma unroll
        for (int w = 0; w < 8; w++) { a0 += s_red[0][w]; a1 += s_red[1][w]; a2 += s_red[2][w]; }
        int base = (bc * 4 + tile) * 3;
        g_part[base + 0] = a0;
        g_part[base + 1] = a1;
        g_part[base + 2] = a2;
    }
}

// ---------------- F2: contract n2 -> k2 ----------------
__global__ void k_f2() {
    __shared__ float s_ct[64], s_st[64];
    if (threadIdx.x < 64) { s_ct[threadIdx.x] = g_ct[threadIdx.x]; s_st[threadIdx.x] = g_st[threadIdx.x]; }
    __syncthreads();
    int bc = blockIdx.x;
    int k1 = threadIdx.x >> 6;
    int n3 = threadIdx.x & 63;
    int base = ((bc * 8 + k1) << 12) + n3;
    float p[8] = {0,0,0,0,0,0,0,0};
    float q[8] = {0,0,0,0,0,0,0,0};
    for (int n2 = 0; n2 < 64; n2++) {
        float acv = g_Ac[base + (n2 << 6)];
        float asv = g_As[base + (n2 << 6)];
        #pragma unroll
        for (int k2 = 0; k2 < 8; k2++) {
            int t = (k2 * n2) & 63;
            float c = s_ct[t], s = s_st[t];
            p[k2] = fmaf(acv, c, fmaf(-asv, s, p[k2]));
            q[k2] = fmaf(acv, s, fmaf( asv, c, q[k2]));
        }
    }
    #pragma unroll
    for (int k2 = 0; k2 < 8; k2++) {
        int o = (((bc * 8 + k1) * 8 + k2) << 6) + n3;
        g_P[o] = p[k2];
        g_Q[o] = q[k2];
    }
}

// ---------------- F3 (+ norm1 finalize): contract n3 -> k3 ----------------
__global__ void k_f3() {
    __shared__ float s_ct[64], s_st[64];
    __shared__ float s_inv;
    int bc = blockIdx.x;
    if (threadIdx.x == 0) {
        float s0 = 0, c0 = 0, c2 = 0;
        #pragma unroll
        for (int tile = 0; tile < 4; tile++) {
            int base = (bc * 4 + tile) * 3;
            s0 += g_part[base + 0];
            c0 += g_part[base + 1];
            c2 += g_part[base + 2];
        }
        float v = (float)NT * (s0 + 0.5f * (c0 - c2));
        s_inv = (v > 0.f) ? rsqrtf(v) : 0.f;
    }
    if (threadIdx.x < 64) { s_ct[threadIdx.x] = g_ct[threadIdx.x]; s_st[threadIdx.x] = g_st[threadIdx.x]; }
    __syncthreads();
    int k1 = threadIdx.x >> 6, k2 = (threadIdx.x >> 3) & 7, k3 = threadIdx.x & 7;
    int base = ((bc * 8 + k1) * 8 + k2) << 6;
    float h = 0.f;
    for (int n3 = 0; n3 < 64; n3++) {
        float pv = g_P[base + n3];
        float qv = g_Q[base + n3];
        int t0 = (k3 * n3) & 63;
        int t1 = (k3 * (n3 + 1)) & 63;
        h += pv * (s_ct[t0] - s_st[t1]) + qv * (s_ct[t1] - s_st[t0]);
    }
    g_x1[bc * 512 + (k1 << 6) + (k2 << 3) + k3] = h * s_inv;
}

// ---------------- conv + norm2 fused ----------------
__global__ void k_conv() {
    int bo = blockIdx.x;
    int b = bo >> 5, o = bo & 31;
    int k = threadIdx.x;
    int k1 = k >> 6, k2 = (k >> 3) & 7, k3 = k & 7;
    int nk = (((8-k1)&7) << 6) | (((8-k2)&7) << 3) | ((8-k3)&7);
    float acc = 0.f;
    for (int i = 0; i < 32; i++) {
        const float* x1p = g_x1 + ((b * 32 + i) << 9);
        int wb = (i * 32 + o) << 9;
        acc = fmaf(x1p[k],  g_wp[wb + k], acc);
        acc = fmaf(x1p[nk], g_wm[wb + k], acc);
    }
    g_y[(bo << 9) + k] = acc;

    __shared__ float sa[512];
    sa[k] = ((k == 0) ? 1.5f : 1.0f) * acc * acc;   // +0.5*y000^2 folded in
    __syncthreads();
    for (int s = 256; s > 0; s >>= 1) {
        if (k < s) sa[k] += sa[k + s];
        __syncthreads();
    }
    if (k == 0) {
        float t = sa[0];
        g_sc2[bo] = (t > 0.f) ? rsqrtf((float)NT * t) / (float)NT : 0.f;
    }
}

// ---------------- I1+I2+I3 fused: expand 8^3 modes -> 64^3 output ----------------
__global__ void __launch_bounds__(256) k_i23(float* __restrict__ out) {
    __shared__ float s_ct[64], s_st[64];
    __shared__ float s_y[512];
    __shared__ float s_tc[4096], s_ts[4096];
    int t = threadIdx.x;
    int tile = blockIdx.x;   // 0..3
    int bo   = blockIdx.y;   // 0..127

    if (t < 64) { s_ct[t] = g_ct[t]; s_st[t] = g_st[t]; }
    float sc = g_sc2[bo];
    s_y[t]       = g_y[(bo << 9) + t]       * sc;
    s_y[t + 256] = g_y[(bo << 9) + t + 256] * sc;
    __syncthreads();

    int j3 = t & 63;
    int jg = t >> 6;   // 0..3

    // stage I1: tc/ts[k1,k2,j3] = sum_k3 y*(U,V)
    {
        float U[8], V[8];
        #pragma unroll
        for (int k3 = 0; k3 < 8; k3++) {
            int t0 = (j3 * k3) & 63;
            int t1 = (j3 * (k3 + 1)) & 63;
            U[k3] = s_ct[t0] - s_st[t1];
            V[k3] = s_ct[t1] - s_st[t0];
        }
        #pragma unroll
        for (int r = 0; r < 16; r++) {
            int kk = jg + 4 * r;   // k1*8+k2 in 0..63
            float a = 0.f, bsum = 0.f;
            #pragma unroll
            for (int k3 = 0; k3 < 8; k3++) {
                float yv = s_y[(kk << 3) + k3];
                a    = fmaf(yv, U[k3], a);
                bsum = fmaf(yv, V[k3], bsum);
            }
            s_tc[(kk << 6) + j3] = a;
            s_ts[(kk << 6) + j3] = bsum;
        }
    }
    __syncthreads();

    float* ob = out + ((size_t)bo << 18);

    #pragma unroll 1
    for (int v = 0; v < 4; v++) {
        int j2 = tile * 16 + jg * 4 + v;
        // stage I2: p[k1], q[k1]
        float p[8], q[8];
        #pragma unroll
        for (int k1 = 0; k1 < 8; k1++) { p[k1] = 0.f; q[k1] = 0.f; }
        #pragma unroll
        for (int k2 = 0; k2 < 8; k2++) {
            int tt = (j2 * k2) & 63;
            float c = s_ct[tt], s = s_st[tt];
            #pragma unroll
            for (int k1 = 0; k1 < 8; k1++) {
                float a = s_tc[((k1 * 8 + k2) << 6) + j3];
                float bb = s_ts[((k1 * 8 + k2) << 6) + j3];
                p[k1] = fmaf(a, c, fmaf(bb,  s, p[k1]));
                q[k1] = fmaf(bb, c, fmaf(-a, s, q[k1]));
            }
        }
        // stage I3 with 4-fold symmetry over j1
        float* op = ob + (j2 << 6) + j3;
        #pragma unroll 1
        for (int j1 = 0; j1 <= 16; j1++) {
            float pce = p[0], pco = 0.f, qse = 0.f, qso = 0.f;
            #pragma unroll
            for (int k = 1; k < 8; k++) {
                int tt = (j1 * k) & 63;
                float c = s_ct[tt], s = s_st[tt];
                if (k & 1) { pco = fmaf(p[k], c, pco); qso = fmaf(q[k], s, qso); }
                else       { pce = fmaf(p[k], c, pce); qse = fmaf(q[k], s, qse); }
            }
            float A = pce + pco, Bv = qse + qso;
            float C = pce - pco, D  = qse - qso;
            op[j1 << 12]                = A + Bv;
            op[((64 - j1) & 63) << 12]  = A - Bv;
            op[((j1 + 32) & 63) << 12]  = C + D;
            op[((32 - j1) & 63) << 12]  = C - D;
        }
    }
}

extern "C" void kernel_launch(void* const* d_in, const int* in_sizes, int n_in,
                              void* d_out, int out_size) {
    const float* x = (const float*)d_in[0];       // (4,32,64,64,64)
    const float* w = (const float*)d_in[1];       // (32,32,8,8,8)
    float* out = (float*)d_out;                   // (4,32,64,64,64)

    k_init_tables<<<1, 64>>>();
    k_prep_w<<<(CC*CC*512 + 255) / 256, 256>>>(w);
    k_f1n<<<dim3(4, NCH), 256>>>(x);
    k_f2<<<NCH, 512>>>();
    k_f3<<<NCH, 512>>>();
    k_conv<<<NCH, 512>>>();
    k_i23<<<dim3(4, NCH), 256>>>(out);
}

// round 3
// speedup vs baseline: 2.5049x; 1.0185x over previous
#include <cuda_runtime.h>
#include <math.h>

#define BB 4
#define CC 32
#define SS 64
#define MM 8
#define NT 262144   // 64^3
#define NCH 128     // B*C

// Scratch (device globals)
__device__ float g_ct[64];
__device__ float g_st[64];
__device__ float g_part[NCH * 4 * 3];     // per (bc,tile): s0,c0,c2
__device__ float g_Ac[NCH*8*64*64];       // 16 MB
__device__ float g_As[NCH*8*64*64];       // 16 MB
__device__ float g_x1[NCH*512];
__device__ float g_y [NCH*512];
__device__ float g_sc2[NCH];
__device__ float g_wp[CC*CC*512];
__device__ float g_wm[CC*CC*512];

// ---------------- tables ----------------
__global__ void k_init_tables() {
    int t = threadIdx.x;
    if (t < 64) {
        double a = (double)t * (M_PI / 32.0);
        g_ct[t] = (float)cos(a);
        g_st[t] = (float)sin(a);
    }
}

// ---------------- weight prep ----------------
__global__ void k_prep_w(const float* __restrict__ w) {
    int idx = blockIdx.x * blockDim.x + threadIdx.x;
    if (idx >= CC*CC*512) return;
    int k  = idx & 511;
    int io = idx >> 9;
    int k1 = k >> 6, k2 = (k >> 3) & 7, k3 = k & 7;
    int nk = (((8-k1)&7) << 6) | (((8-k2)&7) << 3) | ((8-k3)&7);
    float a = w[(io<<9) + k];
    float b = w[(io<<9) + nk];
    g_wp[idx] = 0.5f * (a + b);
    g_wm[idx] = 0.5f * (a - b);
}

// ---------------- F1 + norm1 fused ----------------
// Block handles a self-conjugate set of 16 n2-columns so the reversed reads
// (for C0/C2 correlations) hit lines this block already streams.
__global__ void __launch_bounds__(256, 2) k_f1n(const float* __restrict__ x) {
    __shared__ float s_ct[64], s_st[64];
    __shared__ float s_red[3][8];
    int t = threadIdx.x;
    if (t < 64) { s_ct[t] = g_ct[t]; s_st[t] = g_st[t]; }
    __syncthreads();

    int tile = blockIdx.x;     // 0..3
    int bc   = blockIdx.y;     // 0..127
    int n3   = t & 63;
    int n2g  = t >> 6;         // 0..3
    int r3   = (64 - n3) & 63;
    int r3b  = (62 - n3) & 63;

    const float* xb = x + ((size_t)bc << 18);

    int n2v[4], offp[4], offr0[4], offr2[4];
    #pragma unroll
    for (int v = 0; v < 4; v++) {
        int idx16 = n2g * 4 + v;
        int n2 = (idx16 < 8) ? (tile * 8 + idx16) : (48 - tile * 8 + idx16);
        int r2 = (64 - n2) & 63;
        n2v[v]   = n2;
        offp[v]  = (n2 << 6) + n3;
        offr0[v] = (r2 << 6) + r3;
        offr2[v] = (r2 << 6) + r3b;
    }

    float ac[4][8], as_[4][7];
    #pragma unroll
    for (int v = 0; v < 4; v++) {
        #pragma unroll
        for (int k = 0; k < 8; k++) ac[v][k] = 0.f;
        #pragma unroll
        for (int k = 0; k < 7; k++) as_[v][k] = 0.f;
    }
    float s0 = 0.f, c0 = 0.f, c2 = 0.f;

    for (int n1 = 0; n1 < 64; n1++) {
        int rn1 = (64 - n1) & 63;
        float tc[7], ts[7];
        #pragma unroll
        for (int k = 1; k < 8; k++) {
            int tt = (k * n1) & 63;
            tc[k-1] = s_ct[tt];
            ts[k-1] = s_st[tt];
        }
        int po = n1 << 12, ro = rn1 << 12;
        #pragma unroll
        for (int v = 0; v < 4; v++) {
            float val = xb[po + offp[v]];
            float vr0 = xb[ro + offr0[v]];
            float vr2 = xb[ro + offr2[v]];
            s0 = fmaf(val, val, s0);
            c0 = fmaf(val, vr0, c0);
            c2 = fmaf(val, vr2, c2);
            ac[v][0] += val;
            #pragma unroll
            for (int k = 1; k < 8; k++) {
                ac[v][k]   = fmaf(val, tc[k-1], ac[v][k]);
                as_[v][k-1]= fmaf(val, ts[k-1], as_[v][k-1]);
            }
        }
    }

    // store Ac/As
    #pragma unroll
    for (int v = 0; v < 4; v++) {
        int n2 = n2v[v];
        #pragma unroll
        for (int k = 0; k < 8; k++) {
            int o = (((bc * 8 + k) * 64 + n2) << 6) + n3;
            g_Ac[o] = ac[v][k];
            g_As[o] = (k == 0) ? 0.f : as_[v][k-1];
        }
    }

    // block reduce s0,c0,c2 (deterministic per (bc,tile))
    unsigned m = 0xffffffffu;
    #pragma unroll
    for (int s = 16; s > 0; s >>= 1) {
        s0 += __shfl_down_sync(m, s0, s);
        c0 += __shfl_down_sync(m, c0, s);
        c2 += __shfl_down_sync(m, c2, s);
    }
    int lane = t & 31, wid = t >> 5;
    if (lane == 0) { s_red[0][wid] = s0; s_red[1][wid] = c0; s_red[2][wid] = c2; }
    __syncthreads();
    if (t == 0) {
        float a0 = 0, a1 = 0, a2 = 0;
        #pragma unroll
        for (int w = 0; w < 8; w++) { a0 += s_red[0][w]; a1 += s_red[1][w]; a2 += s_red[2][w]; }
        int base = (bc * 4 + tile) * 3;
        g_part[base + 0] = a0;
        g_part[base + 1] = a1;
        g_part[base + 2] = a2;
    }
}

// ---------------- F2+F3 fused: contract n2 then n3; apply 1/norm1 ----------------
// grid = (8 k1, 128 bc), 512 threads
__global__ void __launch_bounds__(512) k_f23() {
    __shared__ float s_ct[64], s_st[64];
    __shared__ float sAc[4096], sAs[4096];
    __shared__ float sP[512], sQ[512];
    __shared__ float s_inv;

    int t = threadIdx.x;
    int k1 = blockIdx.x;
    int bc = blockIdx.y;

    if (t < 64) { s_ct[t] = g_ct[t]; s_st[t] = g_st[t]; }
    if (t == 0) {
        float s0 = 0, c0 = 0, c2 = 0;
        #pragma unroll
        for (int tile = 0; tile < 4; tile++) {
            int base = (bc * 4 + tile) * 3;
            s0 += g_part[base + 0];
            c0 += g_part[base + 1];
            c2 += g_part[base + 2];
        }
        float v = (float)NT * (s0 + 0.5f * (c0 - c2));
        s_inv = (v > 0.f) ? rsqrtf(v) : 0.f;
    }

    // load Ac/As slab: 4096 floats each, via float4
    {
        const float4* pc = (const float4*)(g_Ac + (((size_t)bc * 8 + k1) << 12));
        const float4* ps = (const float4*)(g_As + (((size_t)bc * 8 + k1) << 12));
        float4* dc = (float4*)sAc;
        float4* ds = (float4*)sAs;
        dc[t]       = pc[t];
        dc[t + 512] = pc[t + 512];
        ds[t]       = ps[t];
        ds[t + 512] = ps[t + 512];
    }
    __syncthreads();

    // stage F2: thread = (k2, n3); contract n2
    {
        int k2 = t >> 6;
        int n3 = t & 63;
        float p = 0.f, q = 0.f;
        #pragma unroll 8
        for (int n2 = 0; n2 < 64; n2++) {
            float acv = sAc[(n2 << 6) + n3];
            float asv = sAs[(n2 << 6) + n3];
            int tt = (k2 * n2) & 63;
            float c = s_ct[tt], s = s_st[tt];
            p = fmaf(acv, c, fmaf(-asv, s, p));
            q = fmaf(acv, s, fmaf( asv, c, q));
        }
        sP[(k2 << 6) + n3] = p;
        sQ[(k2 << 6) + n3] = q;
    }
    __syncthreads();

    // stage F3: 64 threads (k2,k3); contract n3
    if (t < 64) {
        int k2 = t >> 3, k3 = t & 7;
        int base = k2 << 6;
        float h = 0.f;
        #pragma unroll 8
        for (int n3 = 0; n3 < 64; n3++) {
            float pv = sP[base + n3];
            float qv = sQ[base + n3];
            int t0 = (k3 * n3) & 63;
            int t1 = (k3 * (n3 + 1)) & 63;
            h += pv * (s_ct[t0] - s_st[t1]) + qv * (s_ct[t1] - s_st[t0]);
        }
        g_x1[bc * 512 + (k1 << 6) + t] = h * s_inv;
    }
}

// ---------------- conv + norm2 fused ----------------
__global__ void k_conv() {
    int bo = blockIdx.x;
    int b = bo >> 5, o = bo & 31;
    int k = threadIdx.x;
    int k1 = k >> 6, k2 = (k >> 3) & 7, k3 = k & 7;
    int nk = (((8-k1)&7) << 6) | (((8-k2)&7) << 3) | ((8-k3)&7);
    float acc = 0.f;
    for (int i = 0; i < 32; i++) {
        const float* x1p = g_x1 + ((b * 32 + i) << 9);
        int wb = (i * 32 + o) << 9;
        acc = fmaf(x1p[k],  g_wp[wb + k], acc);
        acc = fmaf(x1p[nk], g_wm[wb + k], acc);
    }
    g_y[(bo << 9) + k] = acc;

    __shared__ float sa[512];
    sa[k] = ((k == 0) ? 1.5f : 1.0f) * acc * acc;   // +0.5*y000^2 folded in
    __syncthreads();
    for (int s = 256; s > 0; s >>= 1) {
        if (k < s) sa[k] += sa[k + s];
        __syncthreads();
    }
    if (k == 0) {
        float t = sa[0];
        g_sc2[bo] = (t > 0.f) ? rsqrtf((float)NT * t) / (float)NT : 0.f;
    }
}

// ---------------- I1+I2+I3 fused: expand 8^3 modes -> 64^3 output ----------------
__global__ void __launch_bounds__(256) k_i23(float* __restrict__ out) {
    __shared__ float s_ct[64], s_st[64];
    __shared__ float s_y[512];
    __shared__ float s_tc[4096], s_ts[4096];
    int t = threadIdx.x;
    int tile = blockIdx.x;   // 0..3
    int bo   = blockIdx.y;   // 0..127

    if (t < 64) { s_ct[t] = g_ct[t]; s_st[t] = g_st[t]; }
    float sc = g_sc2[bo];
    s_y[t]       = g_y[(bo << 9) + t]       * sc;
    s_y[t + 256] = g_y[(bo << 9) + t + 256] * sc;
    __syncthreads();

    int j3 = t & 63;
    int jg = t >> 6;   // 0..3

    // stage I1: tc/ts[k1,k2,j3] = sum_k3 y*(U,V)
    {
        float U[8], V[8];
        #pragma unroll
        for (int k3 = 0; k3 < 8; k3++) {
            int t0 = (j3 * k3) & 63;
            int t1 = (j3 * (k3 + 1)) & 63;
            U[k3] = s_ct[t0] - s_st[t1];
            V[k3] = s_ct[t1] - s_st[t0];
        }
        #pragma unroll
        for (int r = 0; r < 16; r++) {
            int kk = jg + 4 * r;   // k1*8+k2 in 0..63
            float a = 0.f, bsum = 0.f;
            #pragma unroll
            for (int k3 = 0; k3 < 8; k3++) {
                float yv = s_y[(kk << 3) + k3];
                a    = fmaf(yv, U[k3], a);
                bsum = fmaf(yv, V[k3], bsum);
            }
            s_tc[(kk << 6) + j3] = a;
            s_ts[(kk << 6) + j3] = bsum;
        }
    }
    __syncthreads();

    float* ob = out + ((size_t)bo << 18);

    #pragma unroll 1
    for (int v = 0; v < 4; v++) {
        int j2 = tile * 16 + jg * 4 + v;
        // stage I2: p[k1], q[k1]
        float p[8], q[8];
        #pragma unroll
        for (int k1 = 0; k1 < 8; k1++) { p[k1] = 0.f; q[k1] = 0.f; }
        #pragma unroll
        for (int k2 = 0; k2 < 8; k2++) {
            int tt = (j2 * k2) & 63;
            float c = s_ct[tt], s = s_st[tt];
            #pragma unroll
            for (int k1 = 0; k1 < 8; k1++) {
                float a = s_tc[((k1 * 8 + k2) << 6) + j3];
                float bb = s_ts[((k1 * 8 + k2) << 6) + j3];
                p[k1] = fmaf(a, c, fmaf(bb,  s, p[k1]));
                q[k1] = fmaf(bb, c, fmaf(-a, s, q[k1]));
            }
        }
        // stage I3 with 4-fold symmetry over j1
        float* op = ob + (j2 << 6) + j3;
        #pragma unroll 1
        for (int j1 = 0; j1 <= 16; j1++) {
            float pce = p[0], pco = 0.f, qse = 0.f, qso = 0.f;
            #pragma unroll
            for (int k = 1; k < 8; k++) {
                int tt = (j1 * k) & 63;
                float c = s_ct[tt], s = s_st[tt];
                if (k & 1) { pco = fmaf(p[k], c, pco); qso = fmaf(q[k], s, qso); }
                else       { pce = fmaf(p[k], c, pce); qse = fmaf(q[k], s, qse); }
            }
            float A = pce + pco, Bv = qse + qso;
            float C = pce - pco, D  = qse - qso;
            op[j1 << 12]                = A + Bv;
            op[((64 - j1) & 63) << 12]  = A - Bv;
            op[((j1 + 32) & 63) << 12]  = C + D;
            op[((32 - j1) & 63) << 12]  = C - D;
        }
    }
}

extern "C" void kernel_launch(void* const* d_in, const int* in_sizes, int n_in,
                              void* d_out, int out_size) {
    const float* x = (const float*)d_in[0];       // (4,32,64,64,64)
    const float* w = (const float*)d_in[1];       // (32,32,8,8,8)
    float* out = (float*)d_out;                   // (4,32,64,64,64)

    k_init_tables<<<1, 64>>>();
    k_prep_w<<<(CC*CC*512 + 255) / 256, 256>>>(w);
    k_f1n<<<dim3(4, NCH), 256>>>(x);
    k_f23<<<dim3(8, NCH), 512>>>();
    k_conv<<<NCH, 512>>>();
    k_i23<<<dim3(4, NCH), 256>>>(out);
}

// round 4
// speedup vs baseline: 3.5142x; 1.4029x over previous
#include <cuda_runtime.h>
#include <math.h>

#define BB 4
#define CC 32
#define SS 64
#define MM 8
#define NT 262144   // 64^3
#define NCH 128     // B*C

// Scratch (device globals)
__device__ float g_ct[64];
__device__ float g_st[64];
__device__ float g_part[NCH * 4 * 3];     // per (bc,tile): s0,c0,c2
__device__ float g_Ac[NCH*8*64*64];       // 16 MB
__device__ float g_As[NCH*8*64*64];       // 16 MB
__device__ float g_x1[NCH*512];
__device__ float g_y [NCH*512];
__device__ float g_sc2[NCH];
__device__ float g_wp[CC*CC*512];
__device__ float g_wm[CC*CC*512];

// ---------------- tables ----------------
__global__ void k_init_tables() {
    int t = threadIdx.x;
    if (t < 64) {
        double a = (double)t * (M_PI / 32.0);
        g_ct[t] = (float)cos(a);
        g_st[t] = (float)sin(a);
    }
}

// ---------------- weight prep ----------------
__global__ void k_prep_w(const float* __restrict__ w) {
    int idx = blockIdx.x * blockDim.x + threadIdx.x;
    if (idx >= CC*CC*512) return;
    int k  = idx & 511;
    int io = idx >> 9;
    int k1 = k >> 6, k2 = (k >> 3) & 7, k3 = k & 7;
    int nk = (((8-k1)&7) << 6) | (((8-k2)&7) << 3) | ((8-k3)&7);
    float a = w[(io<<9) + k];
    float b = w[(io<<9) + nk];
    g_wp[idx] = 0.5f * (a + b);
    g_wm[idx] = 0.5f * (a - b);
}

// ---------------- F1 + norm1 fused, n1-pair symmetry + Chebyshev twiddles ----
__global__ void __launch_bounds__(256, 2) k_f1n(const float* __restrict__ x) {
    __shared__ float s_ct[64], s_st[64];
    __shared__ float s_red[3][8];
    int t = threadIdx.x;
    if (t < 64) { s_ct[t] = g_ct[t]; s_st[t] = g_st[t]; }
    __syncthreads();

    int tile = blockIdx.x;     // 0..3
    int bc   = blockIdx.y;     // 0..127
    int n3   = t & 63;
    int n2g  = t >> 6;         // 0..3
    int r3   = (64 - n3) & 63;
    int r3b  = (62 - n3) & 63;

    const float* xb = x + ((size_t)bc << 18);

    int n2v[4], offp[4], offr0[4], offr2[4];
    #pragma unroll
    for (int v = 0; v < 4; v++) {
        int idx16 = n2g * 4 + v;
        int n2 = (idx16 < 8) ? (tile * 8 + idx16) : (48 - tile * 8 + idx16);
        int r2 = (64 - n2) & 63;
        n2v[v]   = n2;
        offp[v]  = (n2 << 6) + n3;
        offr0[v] = (r2 << 6) + r3;
        offr2[v] = (r2 << 6) + r3b;
    }

    float ac[4][8], as_[4][7];
    #pragma unroll
    for (int v = 0; v < 4; v++) {
        #pragma unroll
        for (int k = 0; k < 8; k++) ac[v][k] = 0.f;
        #pragma unroll
        for (int k = 0; k < 7; k++) as_[v][k] = 0.f;
    }
    float s0 = 0.f, c0 = 0.f, c2 = 0.f;

    // ---- n1 = 0 and n1 = 32 (st = 0) ----
    {
        const int po0 = 0, po32 = 32 << 12;
        #pragma unroll
        for (int v = 0; v < 4; v++) {
            float v0  = xb[po0  + offp[v]];
            float v32 = xb[po32 + offp[v]];
            float u0  = xb[po0  + offr0[v]];
            float u32 = xb[po32 + offr0[v]];
            float z0  = xb[po0  + offr2[v]];
            float z32 = xb[po32 + offr2[v]];
            s0 = fmaf(v0, v0, s0);  s0 = fmaf(v32, v32, s0);
            c0 = fmaf(v0, u0, c0);  c0 = fmaf(v32, u32, c0);
            c2 = fmaf(v0, z0, c2);  c2 = fmaf(v32, z32, c2);
            float sp = v0 + v32, sm = v0 - v32;
            #pragma unroll
            for (int k = 0; k < 8; k++) ac[v][k] += (k & 1) ? sm : sp;
        }
    }

    // ---- pairs n1 = 1..31 with 64-n1 ----
    for (int n1 = 1; n1 < 32; n1++) {
        int rn1 = 64 - n1;
        // Chebyshev twiddles for k=1..7
        float c1 = s_ct[n1], s1 = s_st[n1];
        float tw = c1 + c1;
        float tc[7], ts[7];
        tc[0] = c1; ts[0] = s1;
        tc[1] = fmaf(tw, c1, -1.f);
        ts[1] = tw * s1;
        #pragma unroll
        for (int k = 2; k < 7; k++) {
            tc[k] = fmaf(tw, tc[k-1], -tc[k-2]);
            ts[k] = fmaf(tw, ts[k-1], -ts[k-2]);
        }
        int po = n1 << 12, ro = rn1 << 12;
        #pragma unroll
        for (int v = 0; v < 4; v++) {
            float va = xb[po + offp[v]];
            float vb = xb[ro + offp[v]];
            float ua = xb[po + offr0[v]];
            float ub = xb[ro + offr0[v]];
            float za = xb[po + offr2[v]];
            float zb = xb[ro + offr2[v]];
            s0 = fmaf(va, va, s0);  s0 = fmaf(vb, vb, s0);
            c0 = fmaf(va, ub, c0);  c0 = fmaf(vb, ua, c0);
            c2 = fmaf(va, zb, c2);  c2 = fmaf(vb, za, c2);
            float sp = va + vb, sm = va - vb;
            ac[v][0] += sp;
            #pragma unroll
            for (int k = 1; k < 8; k++) {
                ac[v][k]    = fmaf(sp, tc[k-1], ac[v][k]);
                as_[v][k-1] = fmaf(sm, ts[k-1], as_[v][k-1]);
            }
        }
    }

    // store Ac/As
    #pragma unroll
    for (int v = 0; v < 4; v++) {
        int n2 = n2v[v];
        #pragma unroll
        for (int k = 0; k < 8; k++) {
            int o = (((bc * 8 + k) * 64 + n2) << 6) + n3;
            g_Ac[o] = ac[v][k];
            g_As[o] = (k == 0) ? 0.f : as_[v][k-1];
        }
    }

    // block reduce s0,c0,c2 (deterministic per (bc,tile))
    unsigned m = 0xffffffffu;
    #pragma unroll
    for (int s = 16; s > 0; s >>= 1) {
        s0 += __shfl_down_sync(m, s0, s);
        c0 += __shfl_down_sync(m, c0, s);
        c2 += __shfl_down_sync(m, c2, s);
    }
    int lane = t & 31, wid = t >> 5;
    if (lane == 0) { s_red[0][wid] = s0; s_red[1][wid] = c0; s_red[2][wid] = c2; }
    __syncthreads();
    if (t == 0) {
        float a0 = 0, a1 = 0, a2 = 0;
        #pragma unroll
        for (int w = 0; w < 8; w++) { a0 += s_red[0][w]; a1 += s_red[1][w]; a2 += s_red[2][w]; }
        int base = (bc * 4 + tile) * 3;
        g_part[base + 0] = a0;
        g_part[base + 1] = a1;
        g_part[base + 2] = a2;
    }
}

// ---------------- F2+F3 fused: contract n2 (pair-symmetric, float4) then n3 ----
// grid = (8 k1, 128 bc), 128 threads: t -> (k2 = t>>4, n3g = (t&15)*4)
__global__ void __launch_bounds__(128) k_f23() {
    __shared__ float s_ct[64], s_st[64];
    __shared__ float sAc[4096], sAs[4096];
    __shared__ float sP[512], sQ[512];
    __shared__ float s_inv;

    int t = threadIdx.x;
    int k1 = blockIdx.x;
    int bc = blockIdx.y;

    if (t < 64) { s_ct[t] = g_ct[t]; s_st[t] = g_st[t]; }
    if (t == 0) {
        float s0 = 0, c0 = 0, c2 = 0;
        #pragma unroll
        for (int tile = 0; tile < 4; tile++) {
            int base = (bc * 4 + tile) * 3;
            s0 += g_part[base + 0];
            c0 += g_part[base + 1];
            c2 += g_part[base + 2];
        }
        float v = (float)NT * (s0 + 0.5f * (c0 - c2));
        s_inv = (v > 0.f) ? rsqrtf(v) : 0.f;
    }

    // load Ac/As slab via float4 (8 each per thread)
    {
        const float4* pc = (const float4*)(g_Ac + (((size_t)bc * 8 + k1) << 12));
        const float4* ps = (const float4*)(g_As + (((size_t)bc * 8 + k1) << 12));
        float4* dc = (float4*)sAc;
        float4* ds = (float4*)sAs;
        #pragma unroll
        for (int r = 0; r < 8; r++) {
            dc[t + 128 * r] = pc[t + 128 * r];
            ds[t + 128 * r] = ps[t + 128 * r];
        }
    }
    __syncthreads();

    // stage F2: thread = (k2, 4 n3); contract n2 with pair symmetry
    {
        int k2  = t >> 4;
        int n3g = (t & 15) << 2;
        float4 p, q;
        // n2 = 0: ct=1, st=0
        {
            float4 a = *(const float4*)(sAc + n3g);
            float4 s = *(const float4*)(sAs + n3g);
            p = a; q = s;
        }
        // n2 = 32: ct = (-1)^k2, st=0
        {
            float4 a = *(const float4*)(sAc + (32 << 6) + n3g);
            float4 s = *(const float4*)(sAs + (32 << 6) + n3g);
            float sg = (k2 & 1) ? -1.f : 1.f;
            p.x = fmaf(sg, a.x, p.x); p.y = fmaf(sg, a.y, p.y);
            p.z = fmaf(sg, a.z, p.z); p.w = fmaf(sg, a.w, p.w);
            q.x = fmaf(sg, s.x, q.x); q.y = fmaf(sg, s.y, q.y);
            q.z = fmaf(sg, s.z, q.z); q.w = fmaf(sg, s.w, q.w);
        }
        #pragma unroll 4
        for (int n2 = 1; n2 < 32; n2++) {
            int n2b = 64 - n2;
            int tt = (k2 * n2) & 63;
            float c = s_ct[tt], s = s_st[tt];
            float4 Aa = *(const float4*)(sAc + (n2  << 6) + n3g);
            float4 Ab = *(const float4*)(sAc + (n2b << 6) + n3g);
            float4 Sa = *(const float4*)(sAs + (n2  << 6) + n3g);
            float4 Sb = *(const float4*)(sAs + (n2b << 6) + n3g);
            // p += c*(Aa+Ab) - s*(Sa-Sb);  q += s*(Aa-Ab) + c*(Sa+Sb)
            p.x = fmaf(c, Aa.x + Ab.x, fmaf(-s, Sa.x - Sb.x, p.x));
            p.y = fmaf(c, Aa.y + Ab.y, fmaf(-s, Sa.y - Sb.y, p.y));
            p.z = fmaf(c, Aa.z + Ab.z, fmaf(-s, Sa.z - Sb.z, p.z));
            p.w = fmaf(c, Aa.w + Ab.w, fmaf(-s, Sa.w - Sb.w, p.w));
            q.x = fmaf(s, Aa.x - Ab.x, fmaf(c, Sa.x + Sb.x, q.x));
            q.y = fmaf(s, Aa.y - Ab.y, fmaf(c, Sa.y + Sb.y, q.y));
            q.z = fmaf(s, Aa.z - Ab.z, fmaf(c, Sa.z + Sb.z, q.z));
            q.w = fmaf(s, Aa.w - Ab.w, fmaf(c, Sa.w + Sb.w, q.w));
        }
        *(float4*)(sP + (k2 << 6) + n3g) = p;
        *(float4*)(sQ + (k2 << 6) + n3g) = q;
    }
    __syncthreads();

    // stage F3: 64 threads (k2,k3); contract n3
    if (t < 64) {
        int k2 = t >> 3, k3 = t & 7;
        int base = k2 << 6;
        float h = 0.f;
        #pragma unroll 8
        for (int n3 = 0; n3 < 64; n3++) {
            float pv = sP[base + n3];
            float qv = sQ[base + n3];
            int t0 = (k3 * n3) & 63;
            int t1 = (k3 * (n3 + 1)) & 63;
            h += pv * (s_ct[t0] - s_st[t1]) + qv * (s_ct[t1] - s_st[t0]);
        }
        g_x1[bc * 512 + (k1 << 6) + t] = h * s_inv;
    }
}

// ---------------- conv + norm2 fused ----------------
__global__ void k_conv() {
    int bo = blockIdx.x;
    int b = bo >> 5, o = bo & 31;
    int k = threadIdx.x;
    int k1 = k >> 6, k2 = (k >> 3) & 7, k3 = k & 7;
    int nk = (((8-k1)&7) << 6) | (((8-k2)&7) << 3) | ((8-k3)&7);
    float acc = 0.f;
    for (int i = 0; i < 32; i++) {
        const float* x1p = g_x1 + ((b * 32 + i) << 9);
        int wb = (i * 32 + o) << 9;
        acc = fmaf(x1p[k],  g_wp[wb + k], acc);
        acc = fmaf(x1p[nk], g_wm[wb + k], acc);
    }
    g_y[(bo << 9) + k] = acc;

    __shared__ float sa[512];
    sa[k] = ((k == 0) ? 1.5f : 1.0f) * acc * acc;   // +0.5*y000^2 folded in
    __syncthreads();
    for (int s = 256; s > 0; s >>= 1) {
        if (k < s) sa[k] += sa[k + s];
        __syncthreads();
    }
    if (k == 0) {
        float t = sa[0];
        g_sc2[bo] = (t > 0.f) ? rsqrtf((float)NT * t) / (float)NT : 0.f;
    }
}

// ---------------- I1+I2+I3 fused: expand 8^3 modes -> 64^3 output ----------------
__global__ void __launch_bounds__(256, 2) k_i23(float* __restrict__ out) {
    __shared__ float s_ct[64], s_st[64];
    __shared__ float s_y[512];
    __shared__ float s_tc[4096], s_ts[4096];
    int t = threadIdx.x;
    int tile = blockIdx.x;   // 0..3
    int bo   = blockIdx.y;   // 0..127

    if (t < 64) { s_ct[t] = g_ct[t]; s_st[t] = g_st[t]; }
    float sc = g_sc2[bo];
    s_y[t]       = g_y[(bo << 9) + t]       * sc;
    s_y[t + 256] = g_y[(bo << 9) + t + 256] * sc;
    __syncthreads();

    int j3 = t & 63;
    int jg = t >> 6;   // 0..3

    // stage I1: tc/ts[k1,k2,j3] = sum_k3 y*(U,V)
    {
        float U[8], V[8];
        #pragma unroll
        for (int k3 = 0; k3 < 8; k3++) {
            int t0 = (j3 * k3) & 63;
            int t1 = (j3 * (k3 + 1)) & 63;
            U[k3] = s_ct[t0] - s_st[t1];
            V[k3] = s_ct[t1] - s_st[t0];
        }
        #pragma unroll
        for (int r = 0; r < 16; r++) {
            int kk = jg + 4 * r;   // k1*8+k2 in 0..63
            float a = 0.f, bsum = 0.f;
            #pragma unroll
            for (int k3 = 0; k3 < 8; k3++) {
                float yv = s_y[(kk << 3) + k3];
                a    = fmaf(yv, U[k3], a);
                bsum = fmaf(yv, V[k3], bsum);
            }
            s_tc[(kk << 6) + j3] = a;
            s_ts[(kk << 6) + j3] = bsum;
        }
    }
    __syncthreads();

    float* ob = out + ((size_t)bo << 18);

    // stage I2 for all 4 j2 values into registers
    float p[4][8], q[4][8];
    int j2v[4];
    #pragma unroll
    for (int v = 0; v < 4; v++) {
        int j2 = tile * 16 + jg * 4 + v;
        j2v[v] = j2;
        #pragma unroll
        for (int k1 = 0; k1 < 8; k1++) { p[v][k1] = 0.f; q[v][k1] = 0.f; }
        #pragma unroll
        for (int k2 = 0; k2 < 8; k2++) {
            int tt = (j2 * k2) & 63;
            float c = s_ct[tt], s = s_st[tt];
            #pragma unroll
            for (int k1 = 0; k1 < 8; k1++) {
                float a  = s_tc[((k1 * 8 + k2) << 6) + j3];
                float bb = s_ts[((k1 * 8 + k2) << 6) + j3];
                p[v][k1] = fmaf(a, c, fmaf(bb,  s, p[v][k1]));
                q[v][k1] = fmaf(bb, c, fmaf(-a, s, q[v][k1]));
            }
        }
    }

    // stage I3: j1 outer (trig hoisted), v inner, 4-fold symmetry over j1
    #pragma unroll 1
    for (int j1 = 0; j1 <= 16; j1++) {
        float tcv[7], tsv[7];
        #pragma unroll
        for (int k = 1; k < 8; k++) {
            int tt = (j1 * k) & 63;
            tcv[k-1] = s_ct[tt];
            tsv[k-1] = s_st[tt];
        }
        int o0 = j1 << 12;
        int o1 = ((64 - j1) & 63) << 12;
        int o2 = ((j1 + 32) & 63) << 12;
        int o3 = ((32 - j1) & 63) << 12;
        #pragma unroll
        for (int v = 0; v < 4; v++) {
            float pce = p[v][0], pco = 0.f, qse = 0.f, qso = 0.f;
            #pragma unroll
            for (int k = 1; k < 8; k++) {
                if (k & 1) { pco = fmaf(p[v][k], tcv[k-1], pco); qso = fmaf(q[v][k], tsv[k-1], qso); }
                else       { pce = fmaf(p[v][k], tcv[k-1], pce); qse = fmaf(q[v][k], tsv[k-1], qse); }
            }
            float A = pce + pco, Bv = qse + qso;
            float C = pce - pco, D  = qse - qso;
            float* op = ob + (j2v[v] << 6) + j3;
            op[o0] = A + Bv;
            op[o1] = A - Bv;
            op[o2] = C + D;
            op[o3] = C - D;
        }
    }
}

extern "C" void kernel_launch(void* const* d_in, const int* in_sizes, int n_in,
                              void* d_out, int out_size) {
    const float* x = (const float*)d_in[0];       // (4,32,64,64,64)
    const float* w = (const float*)d_in[1];       // (32,32,8,8,8)
    float* out = (float*)d_out;                   // (4,32,64,64,64)

    k_init_tables<<<1, 64>>>();
    k_prep_w<<<(CC*CC*512 + 255) / 256, 256>>>(w);
    k_f1n<<<dim3(4, NCH), 256>>>(x);
    k_f23<<<dim3(8, NCH), 128>>>();
    k_conv<<<NCH, 512>>>();
    k_i23<<<dim3(4, NCH), 256>>>(out);
}

// round 6
// speedup vs baseline: 3.6398x; 1.0357x over previous
#include <cuda_runtime.h>
#include <math.h>

#define BB 4
#define CC 32
#define SS 64
#define MM 8
#define NT 262144   // 64^3
#define NCH 128     // B*C

// Scratch (device globals)
__device__ float g_ct[64];
__device__ float g_st[64];
__device__ float g_part[NCH * 8 * 3];     // per (bc,tile): s0,c0,c2
__device__ float g_Ac[NCH*8*64*64];       // 16 MB
__device__ float g_As[NCH*8*64*64];       // 16 MB
__device__ float g_x1h[2*NCH*512];        // partial x1, two n3-halves
__device__ float g_y [NCH*512];
__device__ float g_sc2[NCH];
__device__ float g_wp[CC*CC*512];
__device__ float g_wm[CC*CC*512];

// ---------------- weight prep (+ trig tables in block 0) ----------------
__global__ void k_prep_w(const float* __restrict__ w) {
    if (blockIdx.x == 0 && threadIdx.x < 64) {
        int t = threadIdx.x;
        double a = (double)t * (M_PI / 32.0);
        g_ct[t] = (float)cos(a);
        g_st[t] = (float)sin(a);
    }
    int idx = blockIdx.x * blockDim.x + threadIdx.x;
    if (idx >= CC*CC*512) return;
    int k  = idx & 511;
    int io = idx >> 9;
    int k1 = k >> 6, k2 = (k >> 3) & 7, k3 = k & 7;
    int nk = (((8-k1)&7) << 6) | (((8-k2)&7) << 3) | ((8-k3)&7);
    float a = w[(io<<9) + k];
    float b = w[(io<<9) + nk];
    g_wp[idx] = 0.5f * (a + b);
    g_wm[idx] = 0.5f * (a - b);
}

// ---------------- F1 + norm1 fused, n1-pair symmetry + Chebyshev twiddles ----
// 8 self-conjugate n2-tiles of 8 columns; 2 columns/thread; occ target 4 blk/SM
__global__ void __launch_bounds__(256, 4) k_f1n(const float* __restrict__ x) {
    __shared__ float s_ct[64], s_st[64];
    __shared__ float s_red[3][8];
    int t = threadIdx.x;
    if (t < 64) { s_ct[t] = g_ct[t]; s_st[t] = g_st[t]; }
    __syncthreads();

    int tile = blockIdx.x;     // 0..7
    int bc   = blockIdx.y;     // 0..127
    int n3   = t & 63;
    int n2g  = t >> 6;         // 0..3
    int r3   = (64 - n3) & 63;
    int r3b  = (62 - n3) & 63;

    const float* xb = x + ((size_t)bc << 18);

    int n2v[2], offp[2], offr0[2], offr2[2];
    #pragma unroll
    for (int v = 0; v < 2; v++) {
        int idx8 = (n2g << 1) + v;
        int n2;
        if (tile == 0) n2 = (idx8 < 4) ? idx8 : ((idx8 < 7) ? idx8 + 57 : 32);
        else           n2 = (idx8 < 4) ? 4*tile + idx8 : 57 - 4*tile + idx8;
        int r2 = (64 - n2) & 63;
        n2v[v]   = n2;
        offp[v]  = (n2 << 6) + n3;
        offr0[v] = (r2 << 6) + r3;
        offr2[v] = (r2 << 6) + r3b;
    }

    float ac[2][8], as_[2][7];
    #pragma unroll
    for (int v = 0; v < 2; v++) {
        #pragma unroll
        for (int k = 0; k < 8; k++) ac[v][k] = 0.f;
        #pragma unroll
        for (int k = 0; k < 7; k++) as_[v][k] = 0.f;
    }
    float s0 = 0.f, c0 = 0.f, c2 = 0.f;

    // ---- n1 = 0 and n1 = 32 (st = 0) ----
    {
        const int po0 = 0, po32 = 32 << 12;
        #pragma unroll
        for (int v = 0; v < 2; v++) {
            float v0  = xb[po0  + offp[v]];
            float v32 = xb[po32 + offp[v]];
            float u0  = xb[po0  + offr0[v]];
            float u32 = xb[po32 + offr0[v]];
            float z0  = xb[po0  + offr2[v]];
            float z32 = xb[po32 + offr2[v]];
            s0 = fmaf(v0, v0, s0);  s0 = fmaf(v32, v32, s0);
            c0 = fmaf(v0, u0, c0);  c0 = fmaf(v32, u32, c0);
            c2 = fmaf(v0, z0, c2);  c2 = fmaf(v32, z32, c2);
            float sp = v0 + v32, sm = v0 - v32;
            #pragma unroll
            for (int k = 0; k < 8; k++) ac[v][k] += (k & 1) ? sm : sp;
        }
    }

    // ---- pairs n1 = 1..31 with 64-n1 ----
    for (int n1 = 1; n1 < 32; n1++) {
        int rn1 = 64 - n1;
        float c1 = s_ct[n1], s1 = s_st[n1];
        float tw = c1 + c1;
        float tc[7], ts[7];
        tc[0] = c1; ts[0] = s1;
        tc[1] = fmaf(tw, c1, -1.f);
        ts[1] = tw * s1;
        #pragma unroll
        for (int k = 2; k < 7; k++) {
            tc[k] = fmaf(tw, tc[k-1], -tc[k-2]);
            ts[k] = fmaf(tw, ts[k-1], -ts[k-2]);
        }
        int po = n1 << 12, ro = rn1 << 12;
        #pragma unroll
        for (int v = 0; v < 2; v++) {
            float va = xb[po + offp[v]];
            float vb = xb[ro + offp[v]];
            float ua = xb[po + offr0[v]];
            float ub = xb[ro + offr0[v]];
            float za = xb[po + offr2[v]];
            float zb = xb[ro + offr2[v]];
            s0 = fmaf(va, va, s0);  s0 = fmaf(vb, vb, s0);
            c0 = fmaf(va, ub, c0);  c0 = fmaf(vb, ua, c0);
            c2 = fmaf(va, zb, c2);  c2 = fmaf(vb, za, c2);
            float sp = va + vb, sm = va - vb;
            ac[v][0] += sp;
            #pragma unroll
            for (int k = 1; k < 8; k++) {
                ac[v][k]    = fmaf(sp, tc[k-1], ac[v][k]);
                as_[v][k-1] = fmaf(sm, ts[k-1], as_[v][k-1]);
            }
        }
    }

    // store Ac/As
    #pragma unroll
    for (int v = 0; v < 2; v++) {
        int n2 = n2v[v];
        #pragma unroll
        for (int k = 0; k < 8; k++) {
            int o = (((bc * 8 + k) * 64 + n2) << 6) + n3;
            g_Ac[o] = ac[v][k];
            g_As[o] = (k == 0) ? 0.f : as_[v][k-1];
        }
    }

    // block reduce s0,c0,c2
    unsigned m = 0xffffffffu;
    #pragma unroll
    for (int s = 16; s > 0; s >>= 1) {
        s0 += __shfl_down_sync(m, s0, s);
        c0 += __shfl_down_sync(m, c0, s);
        c2 += __shfl_down_sync(m, c2, s);
    }
    int lane = t & 31, wid = t >> 5;
    if (lane == 0) { s_red[0][wid] = s0; s_red[1][wid] = c0; s_red[2][wid] = c2; }
    __syncthreads();
    if (t == 0) {
        float a0 = 0, a1 = 0, a2 = 0;
        #pragma unroll
        for (int w = 0; w < 8; w++) { a0 += s_red[0][w]; a1 += s_red[1][w]; a2 += s_red[2][w]; }
        int base = (bc * 8 + tile) * 3;
        g_part[base + 0] = a0;
        g_part[base + 1] = a1;
        g_part[base + 2] = a2;
    }
}

// ---------------- F2+F3 fused, n3-half slabs for high occupancy ----------------
// grid = (8 k1, 2 half, 128 bc), 128 threads; emits partial x1 per half
__global__ void __launch_bounds__(128) k_f23() {
    __shared__ float s_ct[64], s_st[64];
    __shared__ float sAc[2048], sAs[2048];
    __shared__ float sP[256], sQ[256];
    __shared__ float s_inv;

    int t  = threadIdx.x;
    int k1 = blockIdx.x;
    int h  = blockIdx.y;
    int bc = blockIdx.z;

    if (t < 64) { s_ct[t] = g_ct[t]; s_st[t] = g_st[t]; }
    if (t == 64) {
        float s0 = 0, c0 = 0, c2 = 0;
        #pragma unroll
        for (int tile = 0; tile < 8; tile++) {
            int base = (bc * 8 + tile) * 3;
            s0 += g_part[base + 0];
            c0 += g_part[base + 1];
            c2 += g_part[base + 2];
        }
        float v = (float)NT * (s0 + 0.5f * (c0 - c2));
        s_inv = (v > 0.f) ? rsqrtf(v) : 0.f;
    }

    // load half-slab: 64 rows x 32 floats each array
    {
        const float* pc = g_Ac + (((size_t)bc * 8 + k1) << 12) + (h << 5);
        const float* ps = g_As + (((size_t)bc * 8 + k1) << 12) + (h << 5);
        #pragma unroll
        for (int r = 0; r < 4; r++) {
            int i = t + 128 * r;        // 0..511 float4 slots
            int row = i >> 3, j = i & 7;
            ((float4*)sAc)[(row << 3) + j] = *(const float4*)(pc + (row << 6) + (j << 2));
            ((float4*)sAs)[(row << 3) + j] = *(const float4*)(ps + (row << 6) + (j << 2));
        }
    }
    __syncthreads();

    // stage F2: thread = (k2 = t>>4, 2 n3-locals); contract n2 with pair symmetry
    {
        int k2   = t >> 4;
        int loc2 = (t & 15) << 1;
        float2 p, q;
        {   // n2 = 0
            float2 a = *(const float2*)(sAc + loc2);
            float2 s = *(const float2*)(sAs + loc2);
            p = a; q = s;
        }
        {   // n2 = 32
            float2 a = *(const float2*)(sAc + (32 << 5) + loc2);
            float2 s = *(const float2*)(sAs + (32 << 5) + loc2);
            float sg = (k2 & 1) ? -1.f : 1.f;
            p.x = fmaf(sg, a.x, p.x); p.y = fmaf(sg, a.y, p.y);
            q.x = fmaf(sg, s.x, q.x); q.y = fmaf(sg, s.y, q.y);
        }
        #pragma unroll 4
        for (int n2 = 1; n2 < 32; n2++) {
            int n2b = 64 - n2;
            int tt = (k2 * n2) & 63;
            float c = s_ct[tt], s = s_st[tt];
            float2 Aa = *(const float2*)(sAc + (n2  << 5) + loc2);
            float2 Ab = *(const float2*)(sAc + (n2b << 5) + loc2);
            float2 Sa = *(const float2*)(sAs + (n2  << 5) + loc2);
            float2 Sb = *(const float2*)(sAs + (n2b << 5) + loc2);
            p.x = fmaf(c, Aa.x + Ab.x, fmaf(-s, Sa.x - Sb.x, p.x));
            p.y = fmaf(c, Aa.y + Ab.y, fmaf(-s, Sa.y - Sb.y, p.y));
            q.x = fmaf(s, Aa.x - Ab.x, fmaf(c, Sa.x + Sb.x, q.x));
            q.y = fmaf(s, Aa.y - Ab.y, fmaf(c, Sa.y + Sb.y, q.y));
        }
        *(float2*)(sP + (k2 << 5) + loc2) = p;
        *(float2*)(sQ + (k2 << 5) + loc2) = q;
    }
    __syncthreads();

    // stage F3: 64 threads (k2,k3); contract this n3-half; partial output
    if (t < 64) {
        int k2 = t >> 3, k3 = t & 7;
        int base = k2 << 5;
        float acc = 0.f;
        #pragma unroll 8
        for (int loc = 0; loc < 32; loc++) {
            int n3 = (h << 5) + loc;
            float pv = sP[base + loc];
            float qv = sQ[base + loc];
            int t0 = (k3 * n3) & 63;
            int t1 = (k3 * (n3 + 1)) & 63;
            acc += pv * (s_ct[t0] - s_st[t1]) + qv * (s_ct[t1] - s_st[t0]);
        }
        g_x1h[h * (NCH*512) + bc * 512 + (k1 << 6) + t] = acc * s_inv;
    }
}

// ---------------- conv + norm2 fused (sums the two x1 halves) ----------------
__global__ void k_conv() {
    int bo = blockIdx.x;
    int b = bo >> 5, o = bo & 31;
    int k = threadIdx.x;
    int k1 = k >> 6, k2 = (k >> 3) & 7, k3 = k & 7;
    int nk = (((8-k1)&7) << 6) | (((8-k2)&7) << 3) | ((8-k3)&7);
    float acc = 0.f;
    for (int i = 0; i < 32; i++) {
        const float* xA = g_x1h + ((b * 32 + i) << 9);
        const float* xB = xA + NCH*512;
        int wb = (i * 32 + o) << 9;
        float xk = xA[k]  + xB[k];
        float xn = xA[nk] + xB[nk];
        acc = fmaf(xk, g_wp[wb + k], acc);
        acc = fmaf(xn, g_wm[wb + k], acc);
    }
    g_y[(bo << 9) + k] = acc;

    __shared__ float sa[512];
    sa[k] = ((k == 0) ? 1.5f : 1.0f) * acc * acc;
    __syncthreads();
    for (int s = 256; s > 0; s >>= 1) {
        if (k < s) sa[k] += sa[k + s];
        __syncthreads();
    }
    if (k == 0) {
        float t = sa[0];
        g_sc2[bo] = (t > 0.f) ? rsqrtf((float)NT * t) / (float)NT : 0.f;
    }
}

// ---------------- I1+I2+I3 fused: expand 8^3 modes -> 64^3 output ----------------
__global__ void __launch_bounds__(256, 2) k_i23(float* __restrict__ out) {
    __shared__ float s_ct[64], s_st[64];
    __shared__ float s_y[512];
    __shared__ float s_tc[4096], s_ts[4096];
    int t = threadIdx.x;
    int tile = blockIdx.x;   // 0..3
    int bo   = blockIdx.y;   // 0..127

    if (t < 64) { s_ct[t] = g_ct[t]; s_st[t] = g_st[t]; }
    float sc = g_sc2[bo];
    s_y[t]       = g_y[(bo << 9) + t]       * sc;
    s_y[t + 256] = g_y[(bo << 9) + t + 256] * sc;
    __syncthreads();

    int j3 = t & 63;
    int jg = t >> 6;

    // stage I1
    {
        float U[8], V[8];
        #pragma unroll
        for (int k3 = 0; k3 < 8; k3++) {
            int t0 = (j3 * k3) & 63;
            int t1 = (j3 * (k3 + 1)) & 63;
            U[k3] = s_ct[t0] - s_st[t1];
            V[k3] = s_ct[t1] - s_st[t0];
        }
        #pragma unroll
        for (int r = 0; r < 16; r++) {
            int kk = jg + 4 * r;
            float a = 0.f, bsum = 0.f;
            #pragma unroll
            for (int k3 = 0; k3 < 8; k3++) {
                float yv = s_y[(kk << 3) + k3];
                a    = fmaf(yv, U[k3], a);
                bsum = fmaf(yv, V[k3], bsum);
            }
            s_tc[(kk << 6) + j3] = a;
            s_ts[(kk << 6) + j3] = bsum;
        }
    }
    __syncthreads();

    float* ob = out + ((size_t)bo << 18);

    // stage I2 for all 4 j2 values into registers
    float p[4][8], q[4][8];
    int j2v[4];
    #pragma unroll
    for (int v = 0; v < 4; v++) {
        int j2 = tile * 16 + jg * 4 + v;
        j2v[v] = j2;
        #pragma unroll
        for (int k1 = 0; k1 < 8; k1++) { p[v][k1] = 0.f; q[v][k1] = 0.f; }
        #pragma unroll
        for (int k2 = 0; k2 < 8; k2++) {
            int tt = (j2 * k2) & 63;
            float c = s_ct[tt], s = s_st[tt];
            #pragma unroll
            for (int k1 = 0; k1 < 8; k1++) {
                float a  = s_tc[((k1 * 8 + k2) << 6) + j3];
                float bb = s_ts[((k1 * 8 + k2) << 6) + j3];
                p[v][k1] = fmaf(a, c, fmaf(bb,  s, p[v][k1]));
                q[v][k1] = fmaf(bb, c, fmaf(-a, s, q[v][k1]));
            }
        }
    }

    // stage I3: j1 outer (trig hoisted), 4-fold symmetry over j1
    #pragma unroll 1
    for (int j1 = 0; j1 <= 16; j1++) {
        float tcv[7], tsv[7];
        #pragma unroll
        for (int k = 1; k < 8; k++) {
            int tt = (j1 * k) & 63;
            tcv[k-1] = s_ct[tt];
            tsv[k-1] = s_st[tt];
        }
        int o0 = j1 << 12;
        int o1 = ((64 - j1) & 63) << 12;
        int o2 = ((j1 + 32) & 63) << 12;
        int o3 = ((32 - j1) & 63) << 12;
        #pragma unroll
        for (int v = 0; v < 4; v++) {
            float pce = p[v][0], pco = 0.f, qse = 0.f, qso = 0.f;
            #pragma unroll
            for (int k = 1; k < 8; k++) {
                if (k & 1) { pco = fmaf(p[v][k], tcv[k-1], pco); qso = fmaf(q[v][k], tsv[k-1], qso); }
                else       { pce = fmaf(p[v][k], tcv[k-1], pce); qse = fmaf(q[v][k], tsv[k-1], qse); }
            }
            float A = pce + pco, Bv = qse + qso;
            float C = pce - pco, D  = qse - qso;
            float* op = ob + (j2v[v] << 6) + j3;
            op[o0] = A + Bv;
            op[o1] = A - Bv;
            op[o2] = C + D;
            op[o3] = C - D;
        }
    }
}

extern "C" void kernel_launch(void* const* d_in, const int* in_sizes, int n_in,
                              void* d_out, int out_size) {
    const float* x = (const float*)d_in[0];       // (4,32,64,64,64)
    const float* w = (const float*)d_in[1];       // (32,32,8,8,8)
    float* out = (float*)d_out;                   // (4,32,64,64,64)

    k_prep_w<<<(CC*CC*512 + 255) / 256, 256>>>(w);
    k_f1n<<<dim3(8, NCH), 256>>>(x);
    k_f23<<<dim3(8, 2, NCH), 128>>>();
    k_conv<<<NCH, 512>>>();
    k_i23<<<dim3(4, NCH), 256>>>(out);
}

// round 7
// speedup vs baseline: 3.8657x; 1.0620x over previous
#include <cuda_runtime.h>
#include <math.h>

#define BB 4
#define CC 32
#define SS 64
#define MM 8
#define NT 262144   // 64^3
#define NCH 128     // B*C

// Scratch (device globals)
__device__ float g_ct[64];
__device__ float g_st[64];
__device__ float g_part[NCH * 8 * 3];     // per (bc,tile): s0,c0,c2
__device__ float g_Ac[NCH*8*64*64];       // 16 MB
__device__ float g_As[NCH*8*64*64];       // 16 MB
__device__ float g_x1h[2*NCH*512];        // partial x1, two n3-halves
__device__ float g_yp[4*NCH*512];         // partial y, four i-groups
__device__ float g_wp[CC*CC*512];
__device__ float g_wm[CC*CC*512];

// ---------------- weight prep (+ trig tables in block 0) ----------------
__global__ void k_prep_w(const float* __restrict__ w) {
    if (blockIdx.x == 0 && threadIdx.x < 64) {
        int t = threadIdx.x;
        double a = (double)t * (M_PI / 32.0);
        g_ct[t] = (float)cos(a);
        g_st[t] = (float)sin(a);
    }
    int idx = blockIdx.x * blockDim.x + threadIdx.x;
    if (idx >= CC*CC*512) return;
    int k  = idx & 511;
    int io = idx >> 9;
    int k1 = k >> 6, k2 = (k >> 3) & 7, k3 = k & 7;
    int nk = (((8-k1)&7) << 6) | (((8-k2)&7) << 3) | ((8-k3)&7);
    float a = w[(io<<9) + k];
    float b = w[(io<<9) + nk];
    g_wp[idx] = 0.5f * (a + b);
    g_wm[idx] = 0.5f * (a - b);
}

// ---------------- F1 + norm1 fused, n1-pair symmetry + Chebyshev twiddles ----
__global__ void __launch_bounds__(256, 4) k_f1n(const float* __restrict__ x) {
    __shared__ float s_ct[64], s_st[64];
    __shared__ float s_red[3][8];
    int t = threadIdx.x;
    if (t < 64) { s_ct[t] = g_ct[t]; s_st[t] = g_st[t]; }
    __syncthreads();

    int tile = blockIdx.x;     // 0..7
    int bc   = blockIdx.y;     // 0..127
    int n3   = t & 63;
    int n2g  = t >> 6;         // 0..3
    int r3   = (64 - n3) & 63;
    int r3b  = (62 - n3) & 63;

    const float* xb = x + ((size_t)bc << 18);

    int n2v[2], offp[2], offr0[2], offr2[2];
    #pragma unroll
    for (int v = 0; v < 2; v++) {
        int idx8 = (n2g << 1) + v;
        int n2;
        if (tile == 0) n2 = (idx8 < 4) ? idx8 : ((idx8 < 7) ? idx8 + 57 : 32);
        else           n2 = (idx8 < 4) ? 4*tile + idx8 : 57 - 4*tile + idx8;
        int r2 = (64 - n2) & 63;
        n2v[v]   = n2;
        offp[v]  = (n2 << 6) + n3;
        offr0[v] = (r2 << 6) + r3;
        offr2[v] = (r2 << 6) + r3b;
    }

    float ac[2][8], as_[2][7];
    #pragma unroll
    for (int v = 0; v < 2; v++) {
        #pragma unroll
        for (int k = 0; k < 8; k++) ac[v][k] = 0.f;
        #pragma unroll
        for (int k = 0; k < 7; k++) as_[v][k] = 0.f;
    }
    float s0 = 0.f, c0 = 0.f, c2 = 0.f;

    // ---- n1 = 0 and n1 = 32 (st = 0) ----
    {
        const int po0 = 0, po32 = 32 << 12;
        #pragma unroll
        for (int v = 0; v < 2; v++) {
            float v0  = xb[po0  + offp[v]];
            float v32 = xb[po32 + offp[v]];
            float u0  = xb[po0  + offr0[v]];
            float u32 = xb[po32 + offr0[v]];
            float z0  = xb[po0  + offr2[v]];
            float z32 = xb[po32 + offr2[v]];
            s0 = fmaf(v0, v0, s0);  s0 = fmaf(v32, v32, s0);
            c0 = fmaf(v0, u0, c0);  c0 = fmaf(v32, u32, c0);
            c2 = fmaf(v0, z0, c2);  c2 = fmaf(v32, z32, c2);
            float sp = v0 + v32, sm = v0 - v32;
            #pragma unroll
            for (int k = 0; k < 8; k++) ac[v][k] += (k & 1) ? sm : sp;
        }
    }

    // ---- pairs n1 = 1..31 with 64-n1 ----
    for (int n1 = 1; n1 < 32; n1++) {
        int rn1 = 64 - n1;
        float c1 = s_ct[n1], s1 = s_st[n1];
        float tw = c1 + c1;
        float tc[7], ts[7];
        tc[0] = c1; ts[0] = s1;
        tc[1] = fmaf(tw, c1, -1.f);
        ts[1] = tw * s1;
        #pragma unroll
        for (int k = 2; k < 7; k++) {
            tc[k] = fmaf(tw, tc[k-1], -tc[k-2]);
            ts[k] = fmaf(tw, ts[k-1], -ts[k-2]);
        }
        int po = n1 << 12, ro = rn1 << 12;
        #pragma unroll
        for (int v = 0; v < 2; v++) {
            float va = xb[po + offp[v]];
            float vb = xb[ro + offp[v]];
            float ua = xb[po + offr0[v]];
            float ub = xb[ro + offr0[v]];
            float za = xb[po + offr2[v]];
            float zb = xb[ro + offr2[v]];
            s0 = fmaf(va, va, s0);  s0 = fmaf(vb, vb, s0);
            c0 = fmaf(va, ub, c0);  c0 = fmaf(vb, ua, c0);
            c2 = fmaf(va, zb, c2);  c2 = fmaf(vb, za, c2);
            float sp = va + vb, sm = va - vb;
            ac[v][0] += sp;
            #pragma unroll
            for (int k = 1; k < 8; k++) {
                ac[v][k]    = fmaf(sp, tc[k-1], ac[v][k]);
                as_[v][k-1] = fmaf(sm, ts[k-1], as_[v][k-1]);
            }
        }
    }

    // store Ac/As
    #pragma unroll
    for (int v = 0; v < 2; v++) {
        int n2 = n2v[v];
        #pragma unroll
        for (int k = 0; k < 8; k++) {
            int o = (((bc * 8 + k) * 64 + n2) << 6) + n3;
            g_Ac[o] = ac[v][k];
            g_As[o] = (k == 0) ? 0.f : as_[v][k-1];
        }
    }

    // block reduce s0,c0,c2
    unsigned m = 0xffffffffu;
    #pragma unroll
    for (int s = 16; s > 0; s >>= 1) {
        s0 += __shfl_down_sync(m, s0, s);
        c0 += __shfl_down_sync(m, c0, s);
        c2 += __shfl_down_sync(m, c2, s);
    }
    int lane = t & 31, wid = t >> 5;
    if (lane == 0) { s_red[0][wid] = s0; s_red[1][wid] = c0; s_red[2][wid] = c2; }
    __syncthreads();
    if (t == 0) {
        float a0 = 0, a1 = 0, a2 = 0;
        #pragma unroll
        for (int w = 0; w < 8; w++) { a0 += s_red[0][w]; a1 += s_red[1][w]; a2 += s_red[2][w]; }
        int base = (bc * 8 + tile) * 3;
        g_part[base + 0] = a0;
        g_part[base + 1] = a1;
        g_part[base + 2] = a2;
    }
}

// ---------------- F2+F3 fused, n3-half slabs ----------------
__global__ void __launch_bounds__(128) k_f23() {
    __shared__ float s_ct[64], s_st[64];
    __shared__ float sAc[2048], sAs[2048];
    __shared__ float sP[256], sQ[256];
    __shared__ float s_inv;

    int t  = threadIdx.x;
    int k1 = blockIdx.x;
    int h  = blockIdx.y;
    int bc = blockIdx.z;

    if (t < 64) { s_ct[t] = g_ct[t]; s_st[t] = g_st[t]; }
    if (t == 64) {
        float s0 = 0, c0 = 0, c2 = 0;
        #pragma unroll
        for (int tile = 0; tile < 8; tile++) {
            int base = (bc * 8 + tile) * 3;
            s0 += g_part[base + 0];
            c0 += g_part[base + 1];
            c2 += g_part[base + 2];
        }
        float v = (float)NT * (s0 + 0.5f * (c0 - c2));
        s_inv = (v > 0.f) ? rsqrtf(v) : 0.f;
    }

    // load half-slab: 64 rows x 32 floats each array
    {
        const float* pc = g_Ac + (((size_t)bc * 8 + k1) << 12) + (h << 5);
        const float* ps = g_As + (((size_t)bc * 8 + k1) << 12) + (h << 5);
        #pragma unroll
        for (int r = 0; r < 4; r++) {
            int i = t + 128 * r;
            int row = i >> 3, j = i & 7;
            ((float4*)sAc)[(row << 3) + j] = *(const float4*)(pc + (row << 6) + (j << 2));
            ((float4*)sAs)[(row << 3) + j] = *(const float4*)(ps + (row << 6) + (j << 2));
        }
    }
    __syncthreads();

    // stage F2
    {
        int k2   = t >> 4;
        int loc2 = (t & 15) << 1;
        float2 p, q;
        {   // n2 = 0
            float2 a = *(const float2*)(sAc + loc2);
            float2 s = *(const float2*)(sAs + loc2);
            p = a; q = s;
        }
        {   // n2 = 32
            float2 a = *(const float2*)(sAc + (32 << 5) + loc2);
            float2 s = *(const float2*)(sAs + (32 << 5) + loc2);
            float sg = (k2 & 1) ? -1.f : 1.f;
            p.x = fmaf(sg, a.x, p.x); p.y = fmaf(sg, a.y, p.y);
            q.x = fmaf(sg, s.x, q.x); q.y = fmaf(sg, s.y, q.y);
        }
        #pragma unroll 4
        for (int n2 = 1; n2 < 32; n2++) {
            int n2b = 64 - n2;
            int tt = (k2 * n2) & 63;
            float c = s_ct[tt], s = s_st[tt];
            float2 Aa = *(const float2*)(sAc + (n2  << 5) + loc2);
            float2 Ab = *(const float2*)(sAc + (n2b << 5) + loc2);
            float2 Sa = *(const float2*)(sAs + (n2  << 5) + loc2);
            float2 Sb = *(const float2*)(sAs + (n2b << 5) + loc2);
            p.x = fmaf(c, Aa.x + Ab.x, fmaf(-s, Sa.x - Sb.x, p.x));
            p.y = fmaf(c, Aa.y + Ab.y, fmaf(-s, Sa.y - Sb.y, p.y));
            q.x = fmaf(s, Aa.x - Ab.x, fmaf(c, Sa.x + Sb.x, q.x));
            q.y = fmaf(s, Aa.y - Ab.y, fmaf(c, Sa.y + Sb.y, q.y));
        }
        *(float2*)(sP + (k2 << 5) + loc2) = p;
        *(float2*)(sQ + (k2 << 5) + loc2) = q;
    }
    __syncthreads();

    // stage F3: partial over this n3-half
    if (t < 64) {
        int k2 = t >> 3, k3 = t & 7;
        int base = k2 << 5;
        float acc = 0.f;
        #pragma unroll 8
        for (int loc = 0; loc < 32; loc++) {
            int n3 = (h << 5) + loc;
            float pv = sP[base + loc];
            float qv = sQ[base + loc];
            int t0 = (k3 * n3) & 63;
            int t1 = (k3 * (n3 + 1)) & 63;
            acc += pv * (s_ct[t0] - s_st[t1]) + qv * (s_ct[t1] - s_st[t0]);
        }
        g_x1h[h * (NCH*512) + bc * 512 + (k1 << 6) + t] = acc * s_inv;
    }
}

// ---------------- conv partial: grid (4 ig, 128 bo), 512 thr ----------------
__global__ void __launch_bounds__(512) k_convp() {
    int ig = blockIdx.x;            // 0..3 (i-group of 8)
    int bo = blockIdx.y;            // 0..127
    int b = bo >> 5, o = bo & 31;
    int k = threadIdx.x;
    int k1 = k >> 6, k2 = (k >> 3) & 7, k3 = k & 7;
    int nk = (((8-k1)&7) << 6) | (((8-k2)&7) << 3) | ((8-k3)&7);
    float acc = 0.f;
    #pragma unroll
    for (int ii = 0; ii < 8; ii++) {
        int i = (ig << 3) + ii;
        const float* xA = g_x1h + ((b * 32 + i) << 9);
        const float* xB = xA + NCH*512;
        int wb = (i * 32 + o) << 9;
        float xk = xA[k]  + xB[k];
        float xn = xA[nk] + xB[nk];
        acc = fmaf(xk, g_wp[wb + k], acc);
        acc = fmaf(xn, g_wm[wb + k], acc);
    }
    g_yp[(((ig << 7) | bo) << 9) + k] = acc;
}

// ---------------- I1+I2+I3 fused (+ y assembly + norm2) ----------------
__global__ void __launch_bounds__(256, 2) k_i23(float* __restrict__ out) {
    __shared__ float s_ct[64], s_st[64];
    __shared__ float s_y[512];
    __shared__ float s_tc[4096], s_ts[4096];
    __shared__ float sa[256];
    __shared__ float s_sc;
    int t = threadIdx.x;
    int tile = blockIdx.x;   // 0..3
    int bo   = blockIdx.y;   // 0..127

    if (t < 64) { s_ct[t] = g_ct[t]; s_st[t] = g_st[t]; }

    // assemble y from 4 partials; compute norm2 scale in-block (deterministic)
    float y0 = 0.f, y1 = 0.f;
    #pragma unroll
    for (int ig = 0; ig < 4; ig++) {
        const float* yp = g_yp + (((ig << 7) | bo) << 9);
        y0 += yp[t];
        y1 += yp[t + 256];
    }
    sa[t] = ((t == 0) ? 1.5f : 1.0f) * y0 * y0 + y1 * y1;
    __syncthreads();
    for (int s = 128; s > 0; s >>= 1) {
        if (t < s) sa[t] += sa[t + s];
        __syncthreads();
    }
    if (t == 0) {
        float v = sa[0];
        s_sc = (v > 0.f) ? rsqrtf((float)NT * v) / (float)NT : 0.f;
    }
    __syncthreads();
    s_y[t]       = y0 * s_sc;
    s_y[t + 256] = y1 * s_sc;
    __syncthreads();

    int j3 = t & 63;
    int jg = t >> 6;

    // stage I1
    {
        float U[8], V[8];
        #pragma unroll
        for (int k3 = 0; k3 < 8; k3++) {
            int t0 = (j3 * k3) & 63;
            int t1 = (j3 * (k3 + 1)) & 63;
            U[k3] = s_ct[t0] - s_st[t1];
            V[k3] = s_ct[t1] - s_st[t0];
        }
        #pragma unroll
        for (int r = 0; r < 16; r++) {
            int kk = jg + 4 * r;
            float a = 0.f, bsum = 0.f;
            #pragma unroll
            for (int k3 = 0; k3 < 8; k3++) {
                float yv = s_y[(kk << 3) + k3];
                a    = fmaf(yv, U[k3], a);
                bsum = fmaf(yv, V[k3], bsum);
            }
            s_tc[(kk << 6) + j3] = a;
            s_ts[(kk << 6) + j3] = bsum;
        }
    }
    __syncthreads();

    float* ob = out + ((size_t)bo << 18);

    // stage I2 for all 4 j2 values into registers
    float p[4][8], q[4][8];
    int j2v[4];
    #pragma unroll
    for (int v = 0; v < 4; v++) {
        int j2 = tile * 16 + jg * 4 + v;
        j2v[v] = j2;
        #pragma unroll
        for (int k1 = 0; k1 < 8; k1++) { p[v][k1] = 0.f; q[v][k1] = 0.f; }
        #pragma unroll
        for (int k2 = 0; k2 < 8; k2++) {
            int tt = (j2 * k2) & 63;
            float c = s_ct[tt], s = s_st[tt];
            #pragma unroll
            for (int k1 = 0; k1 < 8; k1++) {
                float a  = s_tc[((k1 * 8 + k2) << 6) + j3];
                float bb = s_ts[((k1 * 8 + k2) << 6) + j3];
                p[v][k1] = fmaf(a, c, fmaf(bb,  s, p[v][k1]));
                q[v][k1] = fmaf(bb, c, fmaf(-a, s, q[v][k1]));
            }
        }
    }

    // stage I3: j1 outer (trig hoisted), 4-fold symmetry over j1
    #pragma unroll 1
    for (int j1 = 0; j1 <= 16; j1++) {
        float tcv[7], tsv[7];
        #pragma unroll
        for (int k = 1; k < 8; k++) {
            int tt = (j1 * k) & 63;
            tcv[k-1] = s_ct[tt];
            tsv[k-1] = s_st[tt];
        }
        int o0 = j1 << 12;
        int o1 = ((64 - j1) & 63) << 12;
        int o2 = ((j1 + 32) & 63) << 12;
        int o3 = ((32 - j1) & 63) << 12;
        #pragma unroll
        for (int v = 0; v < 4; v++) {
            float pce = p[v][0], pco = 0.f, qse = 0.f, qso = 0.f;
            #pragma unroll
            for (int k = 1; k < 8; k++) {
                if (k & 1) { pco = fmaf(p[v][k], tcv[k-1], pco); qso = fmaf(q[v][k], tsv[k-1], qso); }
                else       { pce = fmaf(p[v][k], tcv[k-1], pce); qse = fmaf(q[v][k], tsv[k-1], qse); }
            }
            float A = pce + pco, Bv = qse + qso;
            float C = pce - pco, D  = qse - qso;
            float* op = ob + (j2v[v] << 6) + j3;
            op[o0] = A + Bv;
            op[o1] = A - Bv;
            op[o2] = C + D;
            op[o3] = C - D;
        }
    }
}

extern "C" void kernel_launch(void* const* d_in, const int* in_sizes, int n_in,
                              void* d_out, int out_size) {
    const float* x = (const float*)d_in[0];       // (4,32,64,64,64)
    const float* w = (const float*)d_in[1];       // (32,32,8,8,8)
    float* out = (float*)d_out;                   // (4,32,64,64,64)

    k_prep_w<<<(CC*CC*512 + 255) / 256, 256>>>(w);
    k_f1n<<<dim3(8, NCH), 256>>>(x);
    k_f23<<<dim3(8, 2, NCH), 128>>>();
    k_convp<<<dim3(4, NCH), 512>>>();
    k_i23<<<dim3(4, NCH), 256>>>(out);
}